// round 12
// baseline (speedup 1.0000x reference)
#include <cuda_runtime.h>
#include <cuda_fp16.h>
#include <math.h>

#define B_ 8
#define Q_ 150
#define C_ 134
#define T_ 32
#define H_ 160
#define W_ 160
#define P_ 12544
#define HW_ (H_ * W_)
#define MPAD 192           // Q padded to 3 x 64
#define KSLAB 14
#define KCH 896            // P_/KSLAB
#define NSTAGE 14          // KCH/64

// Static scratch (zero-initialized at module load; rows q>=150 of g_pm are
// never written and stay 0 -> padded GEMM rows contribute nothing).
__device__ __align__(128) __half g_tmT[(size_t)B_ * T_ * P_];      // [b][t][p]
__device__ __align__(128) __half g_pm [(size_t)B_ * MPAD * P_];    // [b][q][p]
__device__ float g_S[B_ * Q_ * 2];                                 // Sneg, Ssig
__device__ float g_Stm[B_ * T_];
// GEMM accumulators: [b][g][row][t]; zeroed by k_prep, RED.F32 from k_gemm.
__device__ __align__(128) float g_AD[B_ * 2 * MPAD * T_];
// Per-batch CTA arrival counters for the fused epilogue (zeroed by k_prep).
__device__ unsigned g_cnt[B_];
// Packed bilinear taps: {base|dx|dy, w00w01 (half2), w10w11 (half2), 0}.
__device__ __align__(128) uint4 g_tap[(size_t)B_ * P_];

// Precompute taps + zero g_AD/g_cnt. Grid (P_/256, B_), 256 threads.
__global__ __launch_bounds__(256) void k_prep(const float* __restrict__ coords) {
    int p = blockIdx.x * 256 + threadIdx.x;
    int b = blockIdx.y;
    int zidx = (b * (P_ / 256) + blockIdx.x) * 256 + threadIdx.x;
    if (zidx < B_ * 2 * MPAD * T_) g_AD[zidx] = 0.f;
    if (zidx < B_) g_cnt[zidx] = 0u;

    float2 c = ((const float2*)coords)[(size_t)b * P_ + p];
    float x = c.x * (float)W_ - 0.5f;
    float y = c.y * (float)H_ - 0.5f;
    float fx = floorf(x), fy = floorf(y);
    float tx = x - fx, ty = y - fy;
    int x0 = (int)fx, y0 = (int)fy;  // in [-1, 159]
    float wx0 = (1.f - tx) * (x0 >= 0 ? 1.f : 0.f);
    float wx1 = tx         * (x0 < W_ - 1 ? 1.f : 0.f);
    float wy0 = (1.f - ty) * (y0 >= 0 ? 1.f : 0.f);
    float wy1 = ty         * (y0 < H_ - 1 ? 1.f : 0.f);
    int xc0 = max(x0, 0), yc0 = max(y0, 0);
    int dx = (x0 >= 0 && x0 < W_ - 1) ? 1 : 0;  // xc1 - xc0
    int dy = (y0 >= 0 && y0 < H_ - 1) ? 1 : 0;  // yc1 - yc0
    int base = yc0 * W_ + xc0;                  // < 25600 (15 bits)
    __half2 wlo = __floats2half2_rn(wx0 * wy0, wx1 * wy0);  // w00, w01
    __half2 whi = __floats2half2_rn(wx0 * wy1, wx1 * wy1);  // w10, w11
    uint4 t;
    t.x = (unsigned)(base | (dx << 15) | (dy << 16));
    t.y = *(unsigned*)&wlo;
    t.z = *(unsigned*)&whi;
    t.w = 0;
    g_tap[(size_t)b * P_ + p] = t;
}

// Paired sampler: each CTA holds TWO consecutive masks in fp16 smem (102.4 KB,
// 2 CTAs/SM x 1024 threads -> 64 warps/SM) and shares one tap load + decode
// across both. Grid (91, B_): bx<16 -> tgt pair (2bx,2bx+1); else pred pair.
__global__ __launch_bounds__(1024, 2) void k_sample(
    const float* __restrict__ pmask, const float* __restrict__ tgt) {
    extern __shared__ __half sh[];           // 2*HW_ halves (two fp16 masks)
    float* swr = (float*)(sh + 2 * HW_);     // 128 floats reduction scratch
    int bx = blockIdx.x, b = blockIdx.y;
    int tid = threadIdx.x;
    bool is_tgt = bx < 16;

    // Two consecutive mask rows are contiguous: one 2*HW_ streaming load.
    const float* src = is_tgt ? tgt + ((size_t)(b * T_ + 2 * bx)) * HW_
                              : pmask + ((size_t)(b * Q_ + 2 * (bx - 16))) * HW_;
    const float4* m4 = (const float4*)src;
    __half2* dst = (__half2*)sh;
    for (int i = tid; i < 2 * HW_ / 4; i += 1024) {
        float4 v = m4[i];
        dst[2 * i]     = __floats2half2_rn(v.x, v.y);
        dst[2 * i + 1] = __floats2half2_rn(v.z, v.w);
    }
    __syncthreads();

    const uint4* taps = g_tap + (size_t)b * P_;
    const __half* m0 = sh;
    const __half* m1 = sh + HW_;

    if (is_tgt) {
        int t0 = 2 * bx;
        __half* out0 = g_tmT + ((size_t)(b * T_ + t0)) * P_;
        __half* out1 = out0 + P_;
        float s0 = 0.f, s1 = 0.f;
        for (int p = tid; p < P_; p += 1024) {
            uint4 tp = taps[p];
            int base = tp.x & 0x7FFF;
            int dx = (tp.x >> 15) & 1;
            int dW = ((tp.x >> 16) & 1) * W_;
            float2 wlo = __half22float2(*(__half2*)&tp.y);
            float2 whi = __half22float2(*(__half2*)&tp.z);
            float v0 = __half2float(m0[base]) * wlo.x
                     + __half2float(m0[base + dx]) * wlo.y
                     + __half2float(m0[base + dW]) * whi.x
                     + __half2float(m0[base + dW + dx]) * whi.y;
            float v1 = __half2float(m1[base]) * wlo.x
                     + __half2float(m1[base + dx]) * wlo.y
                     + __half2float(m1[base + dW]) * whi.x
                     + __half2float(m1[base + dW + dx]) * whi.y;
            out0[p] = __float2half_rn(v0);
            out1[p] = __float2half_rn(v1);
            s0 += v0;
            s1 += v1;
        }
        #pragma unroll
        for (int off = 16; off; off >>= 1) {
            s0 += __shfl_xor_sync(~0u, s0, off);
            s1 += __shfl_xor_sync(~0u, s1, off);
        }
        if ((tid & 31) == 0) { swr[tid >> 5] = s0; swr[32 + (tid >> 5)] = s1; }
        __syncthreads();
        if (tid == 0) {
            float a = 0.f, d = 0.f;
            #pragma unroll
            for (int w = 0; w < 32; w++) { a += swr[w]; d += swr[32 + w]; }
            g_Stm[b * T_ + t0]     = a;
            g_Stm[b * T_ + t0 + 1] = d;
        }
    } else {
        int q0 = 2 * (bx - 16);
        __half* opm0 = g_pm + ((size_t)(b * MPAD + q0)) * P_;
        float n0 = 0.f, g0 = 0.f, n1 = 0.f, g1 = 0.f;
        for (int p = tid; p < P_; p += 1024) {
            uint4 tp = taps[p];
            int base = tp.x & 0x7FFF;
            int dx = (tp.x >> 15) & 1;
            int dW = ((tp.x >> 16) & 1) * W_;
            float2 wlo = __half22float2(*(__half2*)&tp.y);
            float2 whi = __half22float2(*(__half2*)&tp.z);
            float pm0 = __half2float(m0[base]) * wlo.x
                      + __half2float(m0[base + dx]) * wlo.y
                      + __half2float(m0[base + dW]) * whi.x
                      + __half2float(m0[base + dW + dx]) * whi.y;
            float pm1 = __half2float(m1[base]) * wlo.x
                      + __half2float(m1[base + dx]) * wlo.y
                      + __half2float(m1[base + dW]) * whi.x
                      + __half2float(m1[base + dW + dx]) * whi.y;
            // sigmoid pair: 0.5 + 0.5*tanh(pm/2), one f16x2 MUFU
            // (same approx the GEMM uses for D -> consistent, zero-mean error)
            __half2 ph = __floats2half2_rn(0.5f * pm0, 0.5f * pm1);
            unsigned th;
            asm("tanh.approx.f16x2 %0, %1;" : "=r"(th) : "r"(*(unsigned*)&ph));
            __half2 t2 = *(__half2*)&th;
            float sg0 = fmaf(0.5f, __low2float(t2), 0.5f);
            float sg1 = fmaf(0.5f, __high2float(t2), 0.5f);
            // softplus(x) = -log(1 - sigmoid(x)); guard against saturation
            float sp0 = -__logf(fmaxf(1.f - sg0, 1e-7f));
            float sp1 = -__logf(fmaxf(1.f - sg1, 1e-7f));
            n0 += sp0; g0 += sg0;
            n1 += sp1; g1 += sg1;
            opm0[p]      = __float2half_rn(pm0);
            opm0[P_ + p] = __float2half_rn(pm1);
        }
        #pragma unroll
        for (int off = 16; off; off >>= 1) {
            n0 += __shfl_xor_sync(~0u, n0, off);
            g0 += __shfl_xor_sync(~0u, g0, off);
            n1 += __shfl_xor_sync(~0u, n1, off);
            g1 += __shfl_xor_sync(~0u, g1, off);
        }
        if ((tid & 31) == 0) {
            int w = tid >> 5;
            swr[w] = n0; swr[32 + w] = g0; swr[64 + w] = n1; swr[96 + w] = g1;
        }
        __syncthreads();
        if (tid == 0) {
            float a0 = 0.f, d0 = 0.f, a1 = 0.f, d1 = 0.f;
            #pragma unroll
            for (int w = 0; w < 32; w++) {
                a0 += swr[w]; d0 += swr[32 + w]; a1 += swr[64 + w]; d1 += swr[96 + w];
            }
            g_S[(b * Q_ + q0) * 2 + 0] = a0;
            g_S[(b * Q_ + q0) * 2 + 1] = d0;
            g_S[(b * Q_ + q0 + 1) * 2 + 0] = a1;
            g_S[(b * Q_ + q0 + 1) * 2 + 1] = d1;
        }
    }
}

__device__ __forceinline__ void mma16816(float* c, unsigned a0, unsigned a1,
                                         unsigned a2, unsigned a3,
                                         unsigned b0, unsigned b1) {
    asm volatile(
        "mma.sync.aligned.m16n8k16.row.col.f32.f16.f16.f32 "
        "{%0,%1,%2,%3},{%4,%5,%6,%7},{%8,%9},{%0,%1,%2,%3};\n"
        : "+f"(c[0]), "+f"(c[1]), "+f"(c[2]), "+f"(c[3])
        : "r"(a0), "r"(a1), "r"(a2), "r"(a3), "r"(b0), "r"(b1));
}

// sig fragment from pm fragment: 0.5*tanh(x/2)+0.5 elementwise on half2.
__device__ __forceinline__ unsigned sig_h2(unsigned u) {
    __half2 hlf = __float2half2_rn(0.5f);
    __half2 h = __hmul2(*(__half2*)&u, hlf);
    unsigned th;
    asm("tanh.approx.f16x2 %0, %1;" : "=r"(th) : "r"(*(unsigned*)&h));
    __half2 t = __hfma2(*(__half2*)&th, hlf, hlf);
    return *(unsigned*)&t;
}

// Batched split-K GEMM + fused epilogue: stages pm + tm; sig fragments in-reg;
// the last CTA per batch (arrival counter) computes the final costs.
// Grid (3 mblk, KSLAB, B_), 256 threads = 8 warps (4 m-warps x 2 n-warps).
__global__ __launch_bounds__(256) void k_gemm(
    const float* __restrict__ clslog, const int* __restrict__ labels,
    float* __restrict__ out) {
    __shared__ uint4 sApm[2][512];   // 64 rows x 8 granules(16B), XOR-swizzled
    __shared__ uint4 sB[2][256];     // 32 rows x 8 granules
    __shared__ unsigned s_last;
    int mblk = blockIdx.x, ks = blockIdx.y, b = blockIdx.z;
    int tid = threadIdx.x;
    int q0 = mblk * 64;
    size_t baseA = ((size_t)b * MPAD + q0) * P_ + (size_t)ks * KCH;
    size_t baseB = ((size_t)b * T_) * P_ + (size_t)ks * KCH;

    auto stage = [&](int s, int buf) {
        int kg = s * 64;
        #pragma unroll
        for (int i = 0; i < 3; i++) {
            int gid = tid + i * 256;
            const __half* src;
            uint4* dst;
            int r, c;
            if (gid < 512) {
                r = gid >> 3; c = gid & 7;
                src = g_pm + baseA + (size_t)r * P_ + kg + c * 8;
                dst = &sApm[buf][0];
            } else {
                int g2 = gid - 512; r = g2 >> 3; c = g2 & 7;
                src = g_tmT + baseB + (size_t)r * P_ + kg + c * 8;
                dst = &sB[buf][0];
            }
            unsigned d32 = (unsigned)__cvta_generic_to_shared(dst + r * 8 + (c ^ (r & 7)));
            asm volatile("cp.async.cg.shared.global [%0], [%1], 16;\n"
                         :: "r"(d32), "l"(src));
        }
        asm volatile("cp.async.commit_group;\n");
    };

    int warp = tid >> 5, lane = tid & 31;
    int mw = warp >> 1, nw = warp & 1;
    int lm = lane >> 3, l7 = lane & 7;
    int arow = mw * 16 + ((lm & 1) << 3) + l7;   // A ldmatrix row per lane
    int agadd = lm >> 1;                          // k8-half select
    int brow = nw * 16 + ((lm >> 1) << 3) + l7;  // B ldmatrix row per lane
    int bgadd = lm & 1;

    float cA[2][4] = {}, cD[2][4] = {};

    stage(0, 0);
    for (int s = 0; s < NSTAGE; s++) {
        int buf = s & 1;
        if (s + 1 < NSTAGE) {
            stage(s + 1, buf ^ 1);
            asm volatile("cp.async.wait_group 1;\n");
        } else {
            asm volatile("cp.async.wait_group 0;\n");
        }
        __syncthreads();
        unsigned bApm = (unsigned)__cvta_generic_to_shared(&sApm[buf][0]);
        unsigned bBB  = (unsigned)__cvta_generic_to_shared(&sB[buf][0]);
        #pragma unroll
        for (int k16 = 0; k16 < 4; k16++) {
            int ag = (k16 * 2 + agadd) ^ l7;
            int bg = (k16 * 2 + bgadd) ^ l7;
            unsigned aaddr = bApm + ((arow * 8 + ag) << 4);
            unsigned baddr = bBB  + ((brow * 8 + bg) << 4);
            unsigned a0, a1, a2, a3, e0, e1, e2, e3;
            asm volatile("ldmatrix.sync.aligned.m8n8.x4.shared.b16 {%0,%1,%2,%3},[%4];\n"
                         : "=r"(a0), "=r"(a1), "=r"(a2), "=r"(a3) : "r"(aaddr));
            asm volatile("ldmatrix.sync.aligned.m8n8.x4.shared.b16 {%0,%1,%2,%3},[%4];\n"
                         : "=r"(e0), "=r"(e1), "=r"(e2), "=r"(e3) : "r"(baddr));
            unsigned s0 = sig_h2(a0), s1 = sig_h2(a1);
            unsigned s2 = sig_h2(a2), s3 = sig_h2(a3);
            mma16816(cA[0], a0, a1, a2, a3, e0, e1);
            mma16816(cA[1], a0, a1, a2, a3, e2, e3);
            mma16816(cD[0], s0, s1, s2, s3, e0, e1);
            mma16816(cD[1], s0, s1, s2, s3, e2, e3);
        }
        __syncthreads();
    }

    // Epilogue: accumulate into g_AD[b][g][row][t] via RED.F32.
    int r0 = q0 + mw * 16 + (lane >> 2);
    int c0 = 2 * (lane & 3);
    #pragma unroll
    for (int g = 0; g < 2; g++) {
        float (*cc)[4] = g ? cD : cA;
        float* ad = g_AD + ((size_t)(b * 2 + g) * MPAD) * T_;
        #pragma unroll
        for (int nt = 0; nt < 2; nt++) {
            int col = nw * 16 + nt * 8 + c0;
            atomicAdd(&ad[(size_t)r0 * T_ + col],           cc[nt][0]);
            atomicAdd(&ad[(size_t)r0 * T_ + col + 1],       cc[nt][1]);
            atomicAdd(&ad[(size_t)(r0 + 8) * T_ + col],     cc[nt][2]);
            atomicAdd(&ad[(size_t)(r0 + 8) * T_ + col + 1], cc[nt][3]);
        }
    }

    // Fused final: last CTA per batch computes costs for that batch.
    __threadfence();
    if (tid == 0)
        s_last = (atomicAdd(&g_cnt[b], 1u) == 3 * KSLAB - 1) ? 1u : 0u;
    __syncthreads();
    if (!s_last) return;
    __threadfence();

    for (int q = warp; q < Q_; q += 8) {
        float A = g_AD[((size_t)(b * 2 + 0) * MPAD + q) * T_ + lane];
        float D = g_AD[((size_t)(b * 2 + 1) * MPAD + q) * T_ + lane];
        float Sneg = g_S[(b * Q_ + q) * 2 + 0];
        float Ssig = g_S[(b * Q_ + q) * 2 + 1];

        const float* cl = clslog + (size_t)(b * Q_ + q) * C_;
        float lmax = -1e30f;
        for (int c = lane; c < C_; c += 32) lmax = fmaxf(lmax, cl[c]);
        #pragma unroll
        for (int off = 16; off; off >>= 1)
            lmax = fmaxf(lmax, __shfl_xor_sync(~0u, lmax, off));
        float lsum = 0.f;
        for (int c = lane; c < C_; c += 32) lsum += __expf(cl[c] - lmax);
        #pragma unroll
        for (int off = 16; off; off >>= 1)
            lsum += __shfl_xor_sync(~0u, lsum, off);

        int lbl = labels[b * T_ + lane];
        lbl = min(max(lbl, 0), C_ - 1);
        float cost_class = -__expf(cl[lbl] - lmax) / lsum;
        float Stm = g_Stm[b * T_ + lane];
        float cost_mask = 5.f * (Sneg - A) * (1.f / (float)P_);
        float cost_dice = 5.f * (1.f - (2.f * D + 1.f) / (Ssig + Stm + 1.f));
        out[((size_t)(b * Q_ + q)) * T_ + lane] = cost_mask + cost_class + cost_dice;
    }
}

extern "C" void kernel_launch(void* const* d_in, const int* in_sizes, int n_in,
                              void* d_out, int out_size) {
    const float* pmask  = (const float*)d_in[0];  // [8,150,160,160]
    const float* clslog = (const float*)d_in[1];  // [8,150,134]
    const float* tmask  = (const float*)d_in[2];  // [8,32,160,160]
    const int*   labels = (const int*)d_in[3];    // [8,32] int32
    const float* coords = (const float*)d_in[4];  // [8,12544,2]
    float* out = (float*)d_out;                   // [8,150,32]

    const int smemP = 2 * HW_ * 2 + 512;          // two fp16 masks + scratch
    cudaFuncSetAttribute(k_sample, cudaFuncAttributeMaxDynamicSharedMemorySize, smemP);

    k_prep  <<<dim3(P_ / 256, B_), 256>>>(coords);
    k_sample<<<dim3(91, B_), 1024, smemP>>>(pmask, tmask);
    k_gemm  <<<dim3(3, KSLAB, B_), 256>>>(clslog, labels, out);
}

// round 13
// speedup vs baseline: 2.2257x; 2.2257x over previous
#include <cuda_runtime.h>
#include <cuda_fp16.h>
#include <math.h>

#define B_ 8
#define Q_ 150
#define C_ 134
#define T_ 32
#define H_ 160
#define W_ 160
#define P_ 12544
#define HW_ (H_ * W_)
#define MPAD 192           // Q padded to 3 x 64
#define KSLAB 14
#define KCH 896            // P_/KSLAB
#define NSTAGE 14          // KCH/64

// Static scratch (zero-initialized at module load; rows q>=150 of g_pm are
// never written and stay 0 -> padded GEMM rows contribute nothing).
__device__ __align__(128) __half g_tmT[(size_t)B_ * T_ * P_];      // [b][t][p]
__device__ __align__(128) __half g_pm [(size_t)B_ * MPAD * P_];    // [b][q][p]
__device__ float g_S[B_ * Q_ * 2];                                 // Sneg, Ssig
__device__ float g_Stm[B_ * T_];
// GEMM accumulators: [b][g][row][t]; zeroed by k_prep, RED.F32 from k_gemm.
__device__ __align__(128) float g_AD[B_ * 2 * MPAD * T_];
// Packed bilinear taps: {base|dx|dy, w00w01 (half2), w10w11 (half2), 0}.
__device__ __align__(128) uint4 g_tap[(size_t)B_ * P_];

// Precompute taps + zero g_AD. Grid (P_/256, B_), 256 threads.
__global__ __launch_bounds__(256) void k_prep(const float* __restrict__ coords) {
    int p = blockIdx.x * 256 + threadIdx.x;
    int b = blockIdx.y;
    int zidx = (b * (P_ / 256) + blockIdx.x) * 256 + threadIdx.x;
    if (zidx < B_ * 2 * MPAD * T_) g_AD[zidx] = 0.f;

    float2 c = ((const float2*)coords)[(size_t)b * P_ + p];
    float x = c.x * (float)W_ - 0.5f;
    float y = c.y * (float)H_ - 0.5f;
    float fx = floorf(x), fy = floorf(y);
    float tx = x - fx, ty = y - fy;
    int x0 = (int)fx, y0 = (int)fy;  // in [-1, 159]
    float wx0 = (1.f - tx) * (x0 >= 0 ? 1.f : 0.f);
    float wx1 = tx         * (x0 < W_ - 1 ? 1.f : 0.f);
    float wy0 = (1.f - ty) * (y0 >= 0 ? 1.f : 0.f);
    float wy1 = ty         * (y0 < H_ - 1 ? 1.f : 0.f);
    int xc0 = max(x0, 0), yc0 = max(y0, 0);
    int dx = (x0 >= 0 && x0 < W_ - 1) ? 1 : 0;  // xc1 - xc0
    int dy = (y0 >= 0 && y0 < H_ - 1) ? 1 : 0;  // yc1 - yc0
    int base = yc0 * W_ + xc0;                  // < 25600 (15 bits)
    __half2 wlo = __floats2half2_rn(wx0 * wy0, wx1 * wy0);  // w00, w01
    __half2 whi = __floats2half2_rn(wx0 * wy1, wx1 * wy1);  // w10, w11
    uint4 t;
    t.x = (unsigned)(base | (dx << 15) | (dy << 16));
    t.y = *(unsigned*)&wlo;
    t.z = *(unsigned*)&whi;
    t.w = 0;
    g_tap[(size_t)b * P_ + p] = t;
}

// Paired sampler with INTERLEAVED masks: sh2[i] = (m0[i], m1[i]) as half2.
// Same 102.4 KB smem as R11 (2 CTAs/SM, 64 warps/SM) but one LDS.32 serves
// BOTH masks at a tap -> 4 LDS + 4 HFMA2 per sample-pair (was 8 LDS + 16 FFMA).
// Grid (91, B_): bx<16 -> tgt pair (2bx, 2bx+1); else pred pair.
__global__ __launch_bounds__(1024, 2) void k_sample(
    const float* __restrict__ pmask, const float* __restrict__ tgt) {
    extern __shared__ __half2 sh2[];          // HW_ interleaved entries
    float* swr = (float*)(sh2 + HW_);         // 128 floats reduction scratch
    int bx = blockIdx.x, b = blockIdx.y;
    int tid = threadIdx.x;
    bool is_tgt = bx < 16;

    const float* src = is_tgt ? tgt + ((size_t)(b * T_ + 2 * bx)) * HW_
                              : pmask + ((size_t)(b * Q_ + 2 * (bx - 16))) * HW_;
    const float4* m4a = (const float4*)src;          // mask 0
    const float4* m4b = (const float4*)(src + HW_);  // mask 1
    uint4* d4 = (uint4*)sh2;
    for (int i = tid; i < HW_ / 4; i += 1024) {
        float4 a = m4a[i];
        float4 c = m4b[i];
        __half2 p0 = __floats2half2_rn(a.x, c.x);
        __half2 p1 = __floats2half2_rn(a.y, c.y);
        __half2 p2 = __floats2half2_rn(a.z, c.z);
        __half2 p3 = __floats2half2_rn(a.w, c.w);
        uint4 pk;
        pk.x = *(unsigned*)&p0; pk.y = *(unsigned*)&p1;
        pk.z = *(unsigned*)&p2; pk.w = *(unsigned*)&p3;
        d4[i] = pk;
    }
    __syncthreads();

    const uint4* taps = g_tap + (size_t)b * P_;

    if (is_tgt) {
        int t0 = 2 * bx;
        __half* out0 = g_tmT + ((size_t)(b * T_ + t0)) * P_;
        __half* out1 = out0 + P_;
        float s0 = 0.f, s1 = 0.f;
        for (int p = tid; p < P_; p += 1024) {
            uint4 tp = taps[p];
            int base = tp.x & 0x7FFF;
            int dx = (tp.x >> 15) & 1;
            int dW = ((tp.x >> 16) & 1) * W_;
            __half2 wlo = *(__half2*)&tp.y;
            __half2 whi = *(__half2*)&tp.z;
            __half2 v = __hmul2(sh2[base], __low2half2(wlo));
            v = __hfma2(sh2[base + dx],      __high2half2(wlo), v);
            v = __hfma2(sh2[base + dW],      __low2half2(whi),  v);
            v = __hfma2(sh2[base + dW + dx], __high2half2(whi), v);
            out0[p] = __low2half(v);
            out1[p] = __high2half(v);
            float2 vf = __half22float2(v);
            s0 += vf.x;
            s1 += vf.y;
        }
        #pragma unroll
        for (int off = 16; off; off >>= 1) {
            s0 += __shfl_xor_sync(~0u, s0, off);
            s1 += __shfl_xor_sync(~0u, s1, off);
        }
        if ((tid & 31) == 0) { swr[tid >> 5] = s0; swr[32 + (tid >> 5)] = s1; }
        __syncthreads();
        if (tid == 0) {
            float a = 0.f, d = 0.f;
            #pragma unroll
            for (int w = 0; w < 32; w++) { a += swr[w]; d += swr[32 + w]; }
            g_Stm[b * T_ + t0]     = a;
            g_Stm[b * T_ + t0 + 1] = d;
        }
    } else {
        int q0 = 2 * (bx - 16);
        __half* opm0 = g_pm + ((size_t)(b * MPAD + q0)) * P_;
        float n0 = 0.f, g0 = 0.f, n1 = 0.f, g1 = 0.f;
        for (int p = tid; p < P_; p += 1024) {
            uint4 tp = taps[p];
            int base = tp.x & 0x7FFF;
            int dx = (tp.x >> 15) & 1;
            int dW = ((tp.x >> 16) & 1) * W_;
            __half2 wlo = *(__half2*)&tp.y;
            __half2 whi = *(__half2*)&tp.z;
            __half2 v = __hmul2(sh2[base], __low2half2(wlo));
            v = __hfma2(sh2[base + dx],      __high2half2(wlo), v);
            v = __hfma2(sh2[base + dW],      __low2half2(whi),  v);
            v = __hfma2(sh2[base + dW + dx], __high2half2(whi), v);
            opm0[p]      = __low2half(v);
            opm0[P_ + p] = __high2half(v);
            float2 vf = __half22float2(v);
            float pm0 = vf.x, pm1 = vf.y;
            float ea0  = __expf(-fabsf(pm0));
            float r0   = __frcp_rn(1.f + ea0);
            float sg0  = (pm0 >= 0.f) ? r0 : ea0 * r0;
            float sp0  = fmaxf(pm0, 0.f) + __logf(1.f + ea0);
            float ea1  = __expf(-fabsf(pm1));
            float r1   = __frcp_rn(1.f + ea1);
            float sg1  = (pm1 >= 0.f) ? r1 : ea1 * r1;
            float sp1  = fmaxf(pm1, 0.f) + __logf(1.f + ea1);
            n0 += sp0; g0 += sg0;
            n1 += sp1; g1 += sg1;
        }
        #pragma unroll
        for (int off = 16; off; off >>= 1) {
            n0 += __shfl_xor_sync(~0u, n0, off);
            g0 += __shfl_xor_sync(~0u, g0, off);
            n1 += __shfl_xor_sync(~0u, n1, off);
            g1 += __shfl_xor_sync(~0u, g1, off);
        }
        if ((tid & 31) == 0) {
            int w = tid >> 5;
            swr[w] = n0; swr[32 + w] = g0; swr[64 + w] = n1; swr[96 + w] = g1;
        }
        __syncthreads();
        if (tid == 0) {
            float a0 = 0.f, d0 = 0.f, a1 = 0.f, d1 = 0.f;
            #pragma unroll
            for (int w = 0; w < 32; w++) {
                a0 += swr[w]; d0 += swr[32 + w]; a1 += swr[64 + w]; d1 += swr[96 + w];
            }
            g_S[(b * Q_ + q0) * 2 + 0] = a0;
            g_S[(b * Q_ + q0) * 2 + 1] = d0;
            g_S[(b * Q_ + q0 + 1) * 2 + 0] = a1;
            g_S[(b * Q_ + q0 + 1) * 2 + 1] = d1;
        }
    }
}

__device__ __forceinline__ void mma16816(float* c, unsigned a0, unsigned a1,
                                         unsigned a2, unsigned a3,
                                         unsigned b0, unsigned b1) {
    asm volatile(
        "mma.sync.aligned.m16n8k16.row.col.f32.f16.f16.f32 "
        "{%0,%1,%2,%3},{%4,%5,%6,%7},{%8,%9},{%0,%1,%2,%3};\n"
        : "+f"(c[0]), "+f"(c[1]), "+f"(c[2]), "+f"(c[3])
        : "r"(a0), "r"(a1), "r"(a2), "r"(a3), "r"(b0), "r"(b1));
}

// sig fragment from pm fragment: 0.5*tanh(x/2)+0.5 elementwise on half2.
__device__ __forceinline__ unsigned sig_h2(unsigned u) {
    __half2 hlf = __float2half2_rn(0.5f);
    __half2 h = __hmul2(*(__half2*)&u, hlf);
    unsigned th;
    asm("tanh.approx.f16x2 %0, %1;" : "=r"(th) : "r"(*(unsigned*)&h));
    __half2 t = __hfma2(*(__half2*)&th, hlf, hlf);
    return *(unsigned*)&t;
}

// Batched split-K GEMM: stages pm + tm only; sig fragments computed in-register.
// Grid (3 mblk, KSLAB, B_), 256 threads = 8 warps (4 m-warps x 2 n-warps).
__global__ __launch_bounds__(256) void k_gemm() {
    __shared__ uint4 sApm[2][512];   // 64 rows x 8 granules(16B), XOR-swizzled
    __shared__ uint4 sB[2][256];     // 32 rows x 8 granules
    int mblk = blockIdx.x, ks = blockIdx.y, b = blockIdx.z;
    int tid = threadIdx.x;
    int q0 = mblk * 64;
    size_t baseA = ((size_t)b * MPAD + q0) * P_ + (size_t)ks * KCH;
    size_t baseB = ((size_t)b * T_) * P_ + (size_t)ks * KCH;

    auto stage = [&](int s, int buf) {
        int kg = s * 64;
        #pragma unroll
        for (int i = 0; i < 3; i++) {
            int gid = tid + i * 256;
            const __half* src;
            uint4* dst;
            int r, c;
            if (gid < 512) {
                r = gid >> 3; c = gid & 7;
                src = g_pm + baseA + (size_t)r * P_ + kg + c * 8;
                dst = &sApm[buf][0];
            } else {
                int g2 = gid - 512; r = g2 >> 3; c = g2 & 7;
                src = g_tmT + baseB + (size_t)r * P_ + kg + c * 8;
                dst = &sB[buf][0];
            }
            unsigned d32 = (unsigned)__cvta_generic_to_shared(dst + r * 8 + (c ^ (r & 7)));
            asm volatile("cp.async.cg.shared.global [%0], [%1], 16;\n"
                         :: "r"(d32), "l"(src));
        }
        asm volatile("cp.async.commit_group;\n");
    };

    int warp = tid >> 5, lane = tid & 31;
    int mw = warp >> 1, nw = warp & 1;
    int lm = lane >> 3, l7 = lane & 7;
    int arow = mw * 16 + ((lm & 1) << 3) + l7;   // A ldmatrix row per lane
    int agadd = lm >> 1;                          // k8-half select
    int brow = nw * 16 + ((lm >> 1) << 3) + l7;  // B ldmatrix row per lane
    int bgadd = lm & 1;

    float cA[2][4] = {}, cD[2][4] = {};

    stage(0, 0);
    for (int s = 0; s < NSTAGE; s++) {
        int buf = s & 1;
        if (s + 1 < NSTAGE) {
            stage(s + 1, buf ^ 1);
            asm volatile("cp.async.wait_group 1;\n");
        } else {
            asm volatile("cp.async.wait_group 0;\n");
        }
        __syncthreads();
        unsigned bApm = (unsigned)__cvta_generic_to_shared(&sApm[buf][0]);
        unsigned bBB  = (unsigned)__cvta_generic_to_shared(&sB[buf][0]);
        #pragma unroll
        for (int k16 = 0; k16 < 4; k16++) {
            int ag = (k16 * 2 + agadd) ^ l7;
            int bg = (k16 * 2 + bgadd) ^ l7;
            unsigned aaddr = bApm + ((arow * 8 + ag) << 4);
            unsigned baddr = bBB  + ((brow * 8 + bg) << 4);
            unsigned a0, a1, a2, a3, e0, e1, e2, e3;
            asm volatile("ldmatrix.sync.aligned.m8n8.x4.shared.b16 {%0,%1,%2,%3},[%4];\n"
                         : "=r"(a0), "=r"(a1), "=r"(a2), "=r"(a3) : "r"(aaddr));
            asm volatile("ldmatrix.sync.aligned.m8n8.x4.shared.b16 {%0,%1,%2,%3},[%4];\n"
                         : "=r"(e0), "=r"(e1), "=r"(e2), "=r"(e3) : "r"(baddr));
            unsigned s0 = sig_h2(a0), s1 = sig_h2(a1);
            unsigned s2 = sig_h2(a2), s3 = sig_h2(a3);
            mma16816(cA[0], a0, a1, a2, a3, e0, e1);
            mma16816(cA[1], a0, a1, a2, a3, e2, e3);
            mma16816(cD[0], s0, s1, s2, s3, e0, e1);
            mma16816(cD[1], s0, s1, s2, s3, e2, e3);
        }
        __syncthreads();
    }

    // Epilogue: accumulate into g_AD[b][g][row][t] via RED.F32.
    int r0 = q0 + mw * 16 + (lane >> 2);
    int c0 = 2 * (lane & 3);
    #pragma unroll
    for (int g = 0; g < 2; g++) {
        float (*cc)[4] = g ? cD : cA;
        float* ad = g_AD + ((size_t)(b * 2 + g) * MPAD) * T_;
        #pragma unroll
        for (int nt = 0; nt < 2; nt++) {
            int col = nw * 16 + nt * 8 + c0;
            atomicAdd(&ad[(size_t)r0 * T_ + col],           cc[nt][0]);
            atomicAdd(&ad[(size_t)r0 * T_ + col + 1],       cc[nt][1]);
            atomicAdd(&ad[(size_t)(r0 + 8) * T_ + col],     cc[nt][2]);
            atomicAdd(&ad[(size_t)(r0 + 8) * T_ + col + 1], cc[nt][3]);
        }
    }
}

// Final: class cost + combine. Grid (19, B_), 256 threads; one warp per q.
__global__ __launch_bounds__(256) void k_final(
    const float* __restrict__ clslog, const int* __restrict__ labels,
    float* __restrict__ out) {
    int q = blockIdx.x * 8 + (threadIdx.x >> 5);
    int b = blockIdx.y;
    int t = threadIdx.x & 31;
    if (q >= Q_) return;

    float A = g_AD[((size_t)(b * 2 + 0) * MPAD + q) * T_ + t];
    float D = g_AD[((size_t)(b * 2 + 1) * MPAD + q) * T_ + t];
    float Sneg = g_S[(b * Q_ + q) * 2 + 0];
    float Ssig = g_S[(b * Q_ + q) * 2 + 1];

    const float* cl = clslog + (size_t)(b * Q_ + q) * C_;
    float lmax = -1e30f;
    for (int c = t; c < C_; c += 32) lmax = fmaxf(lmax, cl[c]);
    #pragma unroll
    for (int off = 16; off; off >>= 1)
        lmax = fmaxf(lmax, __shfl_xor_sync(~0u, lmax, off));
    float lsum = 0.f;
    for (int c = t; c < C_; c += 32) lsum += __expf(cl[c] - lmax);
    #pragma unroll
    for (int off = 16; off; off >>= 1)
        lsum += __shfl_xor_sync(~0u, lsum, off);

    int lbl = labels[b * T_ + t];
    lbl = min(max(lbl, 0), C_ - 1);
    float cost_class = -__expf(cl[lbl] - lmax) / lsum;
    float Stm = g_Stm[b * T_ + t];
    float cost_mask = 5.f * (Sneg - A) * (1.f / (float)P_);
    float cost_dice = 5.f * (1.f - (2.f * D + 1.f) / (Ssig + Stm + 1.f));
    out[((size_t)(b * Q_ + q)) * T_ + t] = cost_mask + cost_class + cost_dice;
}

extern "C" void kernel_launch(void* const* d_in, const int* in_sizes, int n_in,
                              void* d_out, int out_size) {
    const float* pmask  = (const float*)d_in[0];  // [8,150,160,160]
    const float* clslog = (const float*)d_in[1];  // [8,150,134]
    const float* tmask  = (const float*)d_in[2];  // [8,32,160,160]
    const int*   labels = (const int*)d_in[3];    // [8,32] int32
    const float* coords = (const float*)d_in[4];  // [8,12544,2]
    float* out = (float*)d_out;                   // [8,150,32]

    const int smemP = HW_ * 4 + 512;              // interleaved masks + scratch
    cudaFuncSetAttribute(k_sample, cudaFuncAttributeMaxDynamicSharedMemorySize, smemP);

    k_prep  <<<dim3(P_ / 256, B_), 256>>>(coords);
    k_sample<<<dim3(91, B_), 1024, smemP>>>(pmask, tmask);
    k_gemm  <<<dim3(3, KSLAB, B_), 256>>>();
    k_final <<<dim3(19, B_), 256>>>(clslog, labels, out);
}